// round 13
// baseline (speedup 1.0000x reference)
#include <cuda_runtime.h>
#include <math.h>
#include <stdint.h>

#define D      512
#define H      1024
#define SEQ    4096
#define BATCH  4
#define CHUNK  256
#define NCHUNK 16
#define NROWS  (BATCH * CHUNK)   // 1024 rows per chunk step
#define TOTROWS (BATCH * SEQ)    // 16384 rows total

// ---- chunk GEMM core: 64x64x32, 128 thr, 4 stages ----
#define STAGES    4
#define STG_ELEMS 2304                            // 64*36 == 32*72
#define SMEM_BYTES (STAGES * 2 * STG_ELEMS * 4)   // 73728

// ---- big GEMM core: 128x128x32, 256 thr, 3 stages ----
#define BSTAGES   3
#define BIG_A_ELE (128 * 36)                      // 4608
#define BIG_B_ELE (32 * 136)                      // 4352
#define BIG_SMEM_BYTES (BSTAGES * (BIG_A_ELE + BIG_B_ELE) * 4)   // 107520

// ---------------- scratch ---------------------------------------------------------
__device__ float g_W1[D * H];          // fp32 master
__device__ float g_W2[H * D];
__device__ float g_W1tf[D * H];        // tf32 shadow (GEMM operand)
__device__ float g_W2tf[H * D];
__device__ float g_S1[D * H];
__device__ float g_S2[H * D];
__device__ float g_g2[H * D];
__device__ float g_xtf [TOTROWS * D];
__device__ float g_wktf[D * D];
__device__ float g_wvtf[D * D];
__device__ float g_wqtf[D * D];
__device__ float g_kall[TOTROWS * D];  // tf32 bits
__device__ float g_vall[TOTROWS * D];  // fp32 (epilogue aux)
__device__ float g_q   [TOTROWS * D];  // tf32 bits
__device__ float g_h [NROWS * H];      // fp32 (dgelu aux)
__device__ float g_a [NROWS * H];      // tf32 bits
__device__ float g_e [NROWS * D];      // tf32 bits
__device__ float g_dh[NROWS * H];      // tf32 bits
__device__ float g_af[TOTROWS * H];    // tf32 bits
__device__ unsigned g_bar[2];          // [0]=count, [1]=generation

// ---------------- helpers ---------------------------------------------------------
__device__ __forceinline__ float gelu_exact(float x) {
    return 0.5f * x * (1.0f + erff(x * 0.70710678118654752f));
}
__device__ __forceinline__ float dgelu_exact(float x) {
    return 0.5f * (1.0f + erff(x * 0.70710678118654752f))
         + x * 0.39894228040143268f * expf(-0.5f * x * x);
}
__device__ __forceinline__ uint32_t f2tf(float x) {
    uint32_t u;
    asm("cvt.rna.tf32.f32 %0, %1;" : "=r"(u) : "f"(x));
    return u;
}
__device__ __forceinline__ float f2tff(float x) { return __uint_as_float(f2tf(x)); }
__device__ __forceinline__ float sigm(float x) { return 1.0f / (1.0f + expf(-x)); }
__device__ __forceinline__ int chunk_map(int row, int t) {
    return (row >> 8) * SEQ + t * CHUNK + (row & 255);
}
__device__ __forceinline__ void cp16(uint32_t dst, const void* src) {
    asm volatile("cp.async.cg.shared.global [%0], [%1], 16;" :: "r"(dst), "l"(src));
}
__device__ __forceinline__ void cp_commit() {
    asm volatile("cp.async.commit_group;");
}
template <int N>
__device__ __forceinline__ void cp_wait() {
    asm volatile("cp.async.wait_group %0;" :: "n"(N));
}
__device__ __forceinline__ void mma_tf32(float c[4], const uint32_t a[4], const uint32_t b[2]) {
    asm volatile(
        "mma.sync.aligned.m16n8k8.row.col.f32.tf32.tf32.f32 "
        "{%0,%1,%2,%3}, {%4,%5,%6,%7}, {%8,%9}, {%0,%1,%2,%3};"
        : "+f"(c[0]), "+f"(c[1]), "+f"(c[2]), "+f"(c[3])
        : "r"(a[0]), "r"(a[1]), "r"(a[2]), "r"(a[3]), "r"(b[0]), "r"(b[1]));
}

// grid-wide barrier for persistent kernel.
// writer: __threadfence before arrive (release).
// reader: spin on generation, then __threadfence (gpu-scope => CCTL.IVALL L1
// invalidate per B300 doc) so post-barrier L1 reads see other SMs' writes.
__device__ __forceinline__ void grid_sync() {
    __syncthreads();
    if (threadIdx.x == 0) {
        unsigned gen = *(volatile unsigned*)&g_bar[1];
        __threadfence();
        if (atomicAdd(&g_bar[0], 1u) == gridDim.x - 1) {
            g_bar[0] = 0;
            __threadfence();
            *(volatile unsigned*)&g_bar[1] = gen + 1;
        } else {
            while (*(volatile unsigned*)&g_bar[1] == gen) { __nanosleep(40); }
        }
        __threadfence();
    }
    __syncthreads();
}

#define EPI_NONE     0
#define EPI_GELU_H   1   // aux2 = fp32 preact; C = tf32(gelu)
#define EPI_SUBSCALE 2   // C = tf32((AB - aux)*scale)
#define EPI_DGELU    3   // C = tf32(AB * dgelu(aux))
#define EPI_GRADUP   5   // fused S/W update + tf32 shadow

// ======== chunk GEMM core (64x64x32): operands are tf32 bits ====================
template <bool TA, bool TB, int EPI, bool CHUNKA, bool CHUNKAUX>
__device__ __forceinline__ void gemm_device(
    const float* __restrict__ A, const float* __restrict__ B, float* __restrict__ C,
    int M, int N, int K,
    const float* __restrict__ aux, float* __restrict__ aux2,
    float scale, int chunk_t, int bx, int by,
    float* __restrict__ W, float* __restrict__ S, float* __restrict__ Wtf,
    float alpha, float lr, float decay) {

    extern __shared__ float smem[];
    float* AsBase = smem;
    float* BsBase = smem + STAGES * STG_ELEMS;

    const int tid  = threadIdx.x;
    const int lane = tid & 31;
    const int warp = tid >> 5;
    const int g  = lane >> 2;
    const int tg = lane & 3;
    const int wm = warp >> 1;
    const int wn = warp & 1;
    const int bm = by * 64;
    const int bn = bx * 64;

    const float* pA[4]; int a_kk[4]; int a_sm[4];
    const float* pB[4]; int b_sm[4];
#pragma unroll
    for (int i = 0; i < 4; ++i) {
        int idx = tid + i * 128;
        if (!TA) {
            int row = idx >> 3, c4 = (idx & 7) * 4;
            int grow = bm + row;
            if (CHUNKA) grow = chunk_map(grow, chunk_t);
            pA[i]   = A + (size_t)grow * K + c4;
            a_sm[i] = row * 36 + c4;
            a_kk[i] = 0;
        } else {
            int kk = idx >> 4, m4 = (idx & 15) * 4;
            a_kk[i] = kk;
            pA[i]   = A + bm + m4;
            a_sm[i] = kk * 72 + m4;
        }
        if (!TB) {
            int kb = idx >> 4, n4 = (idx & 15) * 4;
            pB[i]   = B + (size_t)kb * N + bn + n4;
            b_sm[i] = kb * 72 + n4;
        } else {
            int n = idx >> 3, c4 = (idx & 7) * 4;
            pB[i]   = B + (size_t)(bn + n) * K + c4;
            b_sm[i] = n * 36 + c4;
        }
    }

    const uint32_t as_u0 = (uint32_t)__cvta_generic_to_shared(AsBase);
    const uint32_t bs_u0 = (uint32_t)__cvta_generic_to_shared(BsBase);

    auto load_stage = [&](int t8) {
        int s = t8 & (STAGES - 1);
        uint32_t as_u = as_u0 + (uint32_t)(s * STG_ELEMS * 4);
        uint32_t bs_u = bs_u0 + (uint32_t)(s * STG_ELEMS * 4);
        int k0 = t8 << 5;
#pragma unroll
        for (int i = 0; i < 4; ++i) {
            if (!TA) {
                cp16(as_u + a_sm[i] * 4, pA[i] + k0);
            } else {
                int row = k0 + a_kk[i];
                if (CHUNKA) row = chunk_map(row, chunk_t);
                cp16(as_u + a_sm[i] * 4, pA[i] + (size_t)row * M);
            }
        }
#pragma unroll
        for (int i = 0; i < 4; ++i) {
            if (!TB) cp16(bs_u + b_sm[i] * 4, pB[i] + (size_t)k0 * N);
            else     cp16(bs_u + b_sm[i] * 4, pB[i] + k0);
        }
        cp_commit();
    };

    float c[2][4][4] = {};
    auto mmas = [&](int t8) {
        int s = t8 & (STAGES - 1);
        const uint32_t* as = (const uint32_t*)(AsBase + s * STG_ELEMS);
        const uint32_t* bs = (const uint32_t*)(BsBase + s * STG_ELEMS);
#pragma unroll
        for (int kk = 0; kk < 32; kk += 8) {
            uint32_t af[2][4], bf[4][2];
#pragma unroll
            for (int mt = 0; mt < 2; ++mt) {
                int r0 = wm * 32 + mt * 16;
                if (!TA) {
                    af[mt][0] = as[(r0 + g)     * 36 + kk + tg];
                    af[mt][1] = as[(r0 + g + 8) * 36 + kk + tg];
                    af[mt][2] = as[(r0 + g)     * 36 + kk + tg + 4];
                    af[mt][3] = as[(r0 + g + 8) * 36 + kk + tg + 4];
                } else {
                    af[mt][0] = as[(kk + tg)     * 72 + r0 + g];
                    af[mt][1] = as[(kk + tg)     * 72 + r0 + g + 8];
                    af[mt][2] = as[(kk + tg + 4) * 72 + r0 + g];
                    af[mt][3] = as[(kk + tg + 4) * 72 + r0 + g + 8];
                }
            }
#pragma unroll
            for (int nt = 0; nt < 4; ++nt) {
                int cn = wn * 32 + nt * 8 + g;
                if (!TB) {
                    bf[nt][0] = bs[(kk + tg)     * 72 + cn];
                    bf[nt][1] = bs[(kk + tg + 4) * 72 + cn];
                } else {
                    bf[nt][0] = bs[cn * 36 + kk + tg];
                    bf[nt][1] = bs[cn * 36 + kk + tg + 4];
                }
            }
#pragma unroll
            for (int mt = 0; mt < 2; ++mt)
#pragma unroll
                for (int nt = 0; nt < 4; ++nt)
                    mma_tf32(c[mt][nt], af[mt], bf[nt]);
        }
    };

    const int nK = K >> 5;
#pragma unroll
    for (int s = 0; s < STAGES - 1; ++s) load_stage(s);
    for (int t8 = 0; t8 < nK; ++t8) {
        cp_wait<STAGES - 2>();
        __syncthreads();
        if (t8 + STAGES - 1 < nK) load_stage(t8 + STAGES - 1);
        else cp_commit();
        mmas(t8);
    }

#pragma unroll
    for (int mt = 0; mt < 2; ++mt) {
#pragma unroll
        for (int nt = 0; nt < 4; ++nt) {
#pragma unroll
            for (int half = 0; half < 2; ++half) {
                int row = bm + wm * 32 + mt * 16 + g + half * 8;
                int col = bn + wn * 32 + nt * 8 + 2 * tg;
                size_t cidx = (size_t)row * N + col;
                float v0 = c[mt][nt][half * 2 + 0];
                float v1 = c[mt][nt][half * 2 + 1];
                if (EPI == EPI_NONE) {
                    *(float2*)(C + cidx) = make_float2(v0, v1);
                } else if (EPI == EPI_GELU_H) {
                    *(float2*)(aux2 + cidx) = make_float2(v0, v1);
                    *(float2*)(C + cidx) = make_float2(f2tff(gelu_exact(v0)), f2tff(gelu_exact(v1)));
                } else if (EPI == EPI_SUBSCALE) {
                    size_t aidx = CHUNKAUX ? (size_t)chunk_map(row, chunk_t) * N + col : cidx;
                    float2 a2 = *(const float2*)(aux + aidx);
                    *(float2*)(C + cidx) = make_float2(f2tff((v0 - a2.x) * scale),
                                                       f2tff((v1 - a2.y) * scale));
                } else if (EPI == EPI_DGELU) {
                    float2 a2 = *(const float2*)(aux + cidx);
                    *(float2*)(C + cidx) = make_float2(f2tff(v0 * dgelu_exact(a2.x)),
                                                       f2tff(v1 * dgelu_exact(a2.y)));
                } else if (EPI == EPI_GRADUP) {
                    float2 Sv = *(const float2*)(S + cidx);
                    float2 Wv = *(const float2*)(W + cidx);
                    float s0 = decay * Sv.x - lr * v0;
                    float s1 = decay * Sv.y - lr * v1;
                    float w0 = (1.0f - alpha) * Wv.x + s0;
                    float w1 = (1.0f - alpha) * Wv.y + s1;
                    *(float2*)(S + cidx)   = make_float2(s0, s1);
                    *(float2*)(W + cidx)   = make_float2(w0, w1);
                    *(float2*)(Wtf + cidx) = make_float2(f2tff(w0), f2tff(w1));
                }
            }
        }
    }
}

// ======== persistent chunk-loop kernel ==========================================
__global__ void __launch_bounds__(128) chunk_loop_kernel(
    const float* __restrict__ kall, const float* __restrict__ vall,
    float* __restrict__ a, float* __restrict__ h,
    float* __restrict__ e, float* __restrict__ dh, float* __restrict__ g2,
    float* __restrict__ W1, float* __restrict__ S1, float* __restrict__ W1tf,
    float* __restrict__ W2, float* __restrict__ S2, float* __restrict__ W2tf,
    const float* __restrict__ sa, const float* __restrict__ sl,
    const float* __restrict__ sd, const int* __restrict__ um, float escale) {

    if (*um == 0) return;       // reference skips the whole recurrence
    const float alpha = sigm(*sa);
    const float lr    = sigm(*sl);
    const float decay = sigm(*sd);

    for (int t = 0; t < NCHUNK; ++t) {
        // P1: a,h = gelu/pre(k_chunk @ W1)    [16 x 16] = 256 tiles
        for (int tile = blockIdx.x; tile < 256; tile += gridDim.x)
            gemm_device<false, false, EPI_GELU_H, true, false>(
                kall, W1tf, a, NROWS, H, D, nullptr, h, 0.f, t,
                tile & 15, tile >> 4, nullptr, nullptr, nullptr, 0.f, 0.f, 0.f);
        grid_sync();
        // P2: e = tf32((a @ W2 - v_chunk)*escale)   [8 x 16] = 128 tiles
        for (int tile = blockIdx.x; tile < 128; tile += gridDim.x)
            gemm_device<false, false, EPI_SUBSCALE, false, true>(
                a, W2tf, e, NROWS, D, H, vall, nullptr, escale, t,
                tile & 7, tile >> 3, nullptr, nullptr, nullptr, 0.f, 0.f, 0.f);
        grid_sync();
        // P3: dh = tf32((e @ W2^T)*dgelu(h)) [256 tiles] ; g2 = a^T @ e [128 tiles]
        for (int tile = blockIdx.x; tile < 384; tile += gridDim.x) {
            if (tile < 256)
                gemm_device<false, true, EPI_DGELU, false, false>(
                    e, W2tf, dh, NROWS, H, D, h, nullptr, 0.f, 0,
                    tile & 15, tile >> 4, nullptr, nullptr, nullptr, 0.f, 0.f, 0.f);
            else {
                int t2 = tile - 256;
                gemm_device<true, false, EPI_NONE, false, false>(
                    a, e, g2, H, D, NROWS, nullptr, nullptr, 0.f, 0,
                    t2 & 7, t2 >> 3, nullptr, nullptr, nullptr, 0.f, 0.f, 0.f);
            }
        }
        grid_sync();
        // P4: g1 = k_chunk^T @ dh (fused W1/S1 update) [128] ; W2/S2 apply from g2 [128]
        for (int tile = blockIdx.x; tile < 256; tile += gridDim.x) {
            if (tile < 128) {
                gemm_device<true, false, EPI_GRADUP, true, false>(
                    kall, dh, nullptr, D, H, NROWS, nullptr, nullptr, 0.f, t,
                    tile & 15, tile >> 4, W1, S1, W1tf, alpha, lr, decay);
            } else {
                int base = (tile - 128) * 1024 + threadIdx.x;   // float4 index
#pragma unroll
                for (int j = 0; j < 8; ++j) {
                    int f4 = base + j * 128;
                    float4 gv = ((const float4*)g2)[f4];
                    float4 Sv = ((const float4*)S2)[f4];
                    float4 Wv = ((const float4*)W2)[f4];
                    Sv.x = decay * Sv.x - lr * gv.x;  Sv.y = decay * Sv.y - lr * gv.y;
                    Sv.z = decay * Sv.z - lr * gv.z;  Sv.w = decay * Sv.w - lr * gv.w;
                    Wv.x = (1.0f - alpha) * Wv.x + Sv.x;  Wv.y = (1.0f - alpha) * Wv.y + Sv.y;
                    Wv.z = (1.0f - alpha) * Wv.z + Sv.z;  Wv.w = (1.0f - alpha) * Wv.w + Sv.w;
                    ((float4*)S2)[f4] = Sv;
                    ((float4*)W2)[f4] = Wv;
                    ((float4*)W2tf)[f4] = make_float4(f2tff(Wv.x), f2tff(Wv.y),
                                                      f2tff(Wv.z), f2tff(Wv.w));
                }
            }
        }
        grid_sync();
    }
}

// ======== big GEMM core (128x128x32, 256 thr, warp tile 32x64) ==================
template <int EPIB>   // 0 = fp32 store, 1 = tf32 bits, 2 = tf32(gelu)
__device__ __forceinline__ void gemm_big(
    const float* __restrict__ A, const float* __restrict__ B, float* __restrict__ C,
    int N, int K, int bx, int by) {

    extern __shared__ float smem[];
    float* AsBase = smem;
    float* BsBase = smem + BSTAGES * BIG_A_ELE;

    const int tid  = threadIdx.x;
    const int lane = tid & 31;
    const int warp = tid >> 5;
    const int g  = lane >> 2;
    const int tg = lane & 3;
    const int wm = warp >> 1;
    const int wn = warp & 1;
    const int bm = by * 128;
    const int bn = bx * 128;

    const float* pA[4]; int a_sm[4];
    const float* pB[4]; int b_sm[4];
#pragma unroll
    for (int i = 0; i < 4; ++i) {
        int idx = tid + i * 256;
        int row = idx >> 3, c4 = (idx & 7) * 4;
        pA[i]   = A + (size_t)(bm + row) * K + c4;
        a_sm[i] = row * 36 + c4;
        int kb = idx >> 5, n4 = (idx & 31) * 4;
        pB[i]   = B + (size_t)kb * N + bn + n4;
        b_sm[i] = kb * 136 + n4;
    }

    const uint32_t as_u0 = (uint32_t)__cvta_generic_to_shared(AsBase);
    const uint32_t bs_u0 = (uint32_t)__cvta_generic_to_shared(BsBase);

    auto load_stage = [&](int t8, int s) {
        uint32_t as_u = as_u0 + (uint32_t)(s * BIG_A_ELE * 4);
        uint32_t bs_u = bs_u0 + (uint32_t)(s * BIG_B_ELE * 4);
        int k0 = t8 << 5;
#pragma unroll
        for (int i = 0; i < 4; ++i) cp16(as_u + a_sm[i] * 4, pA[i] + k0);
#pragma unroll
        for (int i = 0; i < 4; ++i) cp16(bs_u + b_sm[i] * 4, pB[i] + (size_t)k0 * N);
        cp_commit();
    };

    float c[2][8][4] = {};
    auto mmas = [&](int s) {
        const uint32_t* as = (const uint32_t*)(AsBase + s * BIG_A_ELE);
        const uint32_t* bs = (const uint32_t*)(BsBase + s * BIG_B_ELE);
#pragma unroll
        for (int kk = 0; kk < 32; kk += 8) {
            uint32_t af[2][4], bf[8][2];
#pragma unroll
            for (int mt = 0; mt < 2; ++mt) {
                int r0 = wm * 32 + mt * 16;
                af[mt][0] = as[(r0 + g)     * 36 + kk + tg];
                af[mt][1] = as[(r0 + g + 8) * 36 + kk + tg];
                af[mt][2] = as[(r0 + g)     * 36 + kk + tg + 4];
                af[mt][3] = as[(r0 + g + 8) * 36 + kk + tg + 4];
            }
#pragma unroll
            for (int nt = 0; nt < 8; ++nt) {
                int cn = wn * 64 + nt * 8 + g;
                bf[nt][0] = bs[(kk + tg)     * 136 + cn];
                bf[nt][1] = bs[(kk + tg + 4) * 136 + cn];
            }
#pragma unroll
            for (int mt = 0; mt < 2; ++mt)
#pragma unroll
                for (int nt = 0; nt < 8; ++nt)
                    mma_tf32(c[mt][nt], af[mt], bf[nt]);
        }
    };

    const int nK = K >> 5;
    load_stage(0, 0);
    load_stage(1, 1);
    for (int t8 = 0; t8 < nK; ++t8) {
        cp_wait<BSTAGES - 2>();
        __syncthreads();
        int nxt = t8 + BSTAGES - 1;
        if (nxt < nK) load_stage(nxt, nxt % BSTAGES);
        else cp_commit();
        mmas(t8 % BSTAGES);
    }

#pragma unroll
    for (int mt = 0; mt < 2; ++mt) {
#pragma unroll
        for (int nt = 0; nt < 8; ++nt) {
#pragma unroll
            for (int half = 0; half < 2; ++half) {
                int row = bm + wm * 32 + mt * 16 + g + half * 8;
                int col = bn + wn * 64 + nt * 8 + 2 * tg;
                size_t cidx = (size_t)row * N + col;
                float v0 = c[mt][nt][half * 2 + 0];
                float v1 = c[mt][nt][half * 2 + 1];
                if (EPIB == 0)      *(float2*)(C + cidx) = make_float2(v0, v1);
                else if (EPIB == 1) *(float2*)(C + cidx) = make_float2(f2tff(v0), f2tff(v1));
                else                *(float2*)(C + cidx) = make_float2(f2tff(gelu_exact(v0)),
                                                                      f2tff(gelu_exact(v1)));
            }
        }
    }
}

// ======== global kernels ========================================================
#define X4   (TOTROWS * D / 4)    // 2097152
#define WW4  (D * D / 4)          // 65536
#define W14  (D * H / 4)          // 131072
#define CVT_TOTAL (X4 + 3 * WW4 + 2 * W14)   // 2555904

__global__ void __launch_bounds__(256) cvt_all_kernel(
    const float4* __restrict__ x, const float4* __restrict__ wk,
    const float4* __restrict__ wv, const float4* __restrict__ wq,
    const float4* __restrict__ w1, const float4* __restrict__ w2,
    float4* __restrict__ xo, float4* __restrict__ wko, float4* __restrict__ wvo,
    float4* __restrict__ wqo, float4* __restrict__ w1o, float4* __restrict__ w2o) {
    int i = blockIdx.x * blockDim.x + threadIdx.x;
    if (i >= CVT_TOTAL) return;
    const float4* src; float4* dst; int off;
    if (i < X4)                            { src = x;  dst = xo;  off = i; }
    else if (i < X4 + WW4)                 { src = wk; dst = wko; off = i - X4; }
    else if (i < X4 + 2 * WW4)             { src = wv; dst = wvo; off = i - X4 - WW4; }
    else if (i < X4 + 3 * WW4)             { src = wq; dst = wqo; off = i - X4 - 2 * WW4; }
    else if (i < X4 + 3 * WW4 + W14)       { src = w1; dst = w1o; off = i - X4 - 3 * WW4; }
    else                                   { src = w2; dst = w2o; off = i - X4 - 3 * WW4 - W14; }
    float4 v = src[off];
    dst[off] = make_float4(f2tff(v.x), f2tff(v.y), f2tff(v.z), f2tff(v.w));
}

__global__ void __launch_bounds__(256) proj_kernel(
    const float* __restrict__ xtf, const float* __restrict__ wktf,
    const float* __restrict__ wvtf, const float* __restrict__ wqtf,
    float* __restrict__ kall, float* __restrict__ vall, float* __restrict__ q) {
    if (blockIdx.z == 0)
        gemm_big<1>(xtf, wktf, kall, D, D, blockIdx.x, blockIdx.y);
    else if (blockIdx.z == 1)
        gemm_big<0>(xtf, wvtf, vall, D, D, blockIdx.x, blockIdx.y);
    else
        gemm_big<1>(xtf, wqtf, q, D, D, blockIdx.x, blockIdx.y);
}

__global__ void __launch_bounds__(256) ro1_kernel(
    const float* __restrict__ q, const float* __restrict__ W1tf, float* __restrict__ af) {
    gemm_big<2>(q, W1tf, af, H, D, blockIdx.x, blockIdx.y);
}
__global__ void __launch_bounds__(256) ro2_kernel(
    const float* __restrict__ af, const float* __restrict__ W2tf, float* __restrict__ out) {
    gemm_big<0>(af, W2tf, out, D, H, blockIdx.x, blockIdx.y);
}

// ---------------- launch ---------------------------------------------------------
extern "C" void kernel_launch(void* const* d_in, const int* in_sizes, int n_in,
                              void* d_out, int out_size) {
    const float* x    = (const float*)d_in[0];
    const float* w_q  = (const float*)d_in[1];
    const float* w_k  = (const float*)d_in[2];
    const float* w_v  = (const float*)d_in[3];
    const float* mw1  = (const float*)d_in[4];
    const float* mw2  = (const float*)d_in[5];
    const float* a_t  = (const float*)d_in[6];
    const float* l_t  = (const float*)d_in[7];
    const float* dc_t = (const float*)d_in[8];
    const int*   um   = (const int*)  d_in[9];
    float* out = (float*)d_out;

    static int pers_grid = 0;
    if (!pers_grid) {
        cudaFuncSetAttribute(proj_kernel, cudaFuncAttributeMaxDynamicSharedMemorySize, BIG_SMEM_BYTES);
        cudaFuncSetAttribute(ro1_kernel,  cudaFuncAttributeMaxDynamicSharedMemorySize, BIG_SMEM_BYTES);
        cudaFuncSetAttribute(ro2_kernel,  cudaFuncAttributeMaxDynamicSharedMemorySize, BIG_SMEM_BYTES);
        cudaFuncSetAttribute(chunk_loop_kernel, cudaFuncAttributeMaxDynamicSharedMemorySize, SMEM_BYTES);
        int per_sm = 0;
        cudaOccupancyMaxActiveBlocksPerMultiprocessor(&per_sm, chunk_loop_kernel, 128, SMEM_BYTES);
        if (per_sm < 1) per_sm = 1;
        int dev = 0, sms = 0;
        cudaGetDevice(&dev);
        cudaDeviceGetAttribute(&sms, cudaDevAttrMultiProcessorCount, dev);
        pers_grid = per_sm * sms;        // guaranteed co-resident
    }

    float *W1, *W2, *W1tf, *W2tf, *S1, *S2, *g2, *xtf, *wktf, *wvtf, *wqtf;
    float *kall, *vall, *q_, *h_, *a_, *e_, *dh_, *af_;
    unsigned* bar;
    cudaGetSymbolAddress((void**)&W1,   g_W1);
    cudaGetSymbolAddress((void**)&W2,   g_W2);
    cudaGetSymbolAddress((void**)&W1tf, g_W1tf);
    cudaGetSymbolAddress((void**)&W2tf, g_W2tf);
    cudaGetSymbolAddress((void**)&S1,   g_S1);
    cudaGetSymbolAddress((void**)&S2,   g_S2);
    cudaGetSymbolAddress((void**)&g2,   g_g2);
    cudaGetSymbolAddress((void**)&xtf,  g_xtf);
    cudaGetSymbolAddress((void**)&wktf, g_wktf);
    cudaGetSymbolAddress((void**)&wvtf, g_wvtf);
    cudaGetSymbolAddress((void**)&wqtf, g_wqtf);
    cudaGetSymbolAddress((void**)&kall, g_kall);
    cudaGetSymbolAddress((void**)&vall, g_vall);
    cudaGetSymbolAddress((void**)&q_,   g_q);
    cudaGetSymbolAddress((void**)&h_,   g_h);
    cudaGetSymbolAddress((void**)&a_,   g_a);
    cudaGetSymbolAddress((void**)&e_,   g_e);
    cudaGetSymbolAddress((void**)&dh_,  g_dh);
    cudaGetSymbolAddress((void**)&af_,  g_af);
    cudaGetSymbolAddress((void**)&bar,  g_bar);

    cudaMemcpyAsync(W1, mw1, sizeof(float) * D * H, cudaMemcpyDeviceToDevice);
    cudaMemcpyAsync(W2, mw2, sizeof(float) * H * D, cudaMemcpyDeviceToDevice);
    cudaMemsetAsync(S1, 0, sizeof(float) * D * H);
    cudaMemsetAsync(S2, 0, sizeof(float) * H * D);
    cudaMemsetAsync(bar, 0, 2 * sizeof(unsigned));

    cvt_all_kernel<<<(CVT_TOTAL + 255) / 256, 256>>>(
        (const float4*)x, (const float4*)w_k, (const float4*)w_v, (const float4*)w_q,
        (const float4*)mw1, (const float4*)mw2,
        (float4*)xtf, (float4*)wktf, (float4*)wvtf, (float4*)wqtf,
        (float4*)W1tf, (float4*)W2tf);

    const float escale = 2.0f / (float)(NROWS * D);

    proj_kernel<<<dim3(D / 128, TOTROWS / 128, 3), 256, BIG_SMEM_BYTES>>>(
        xtf, wktf, wvtf, wqtf, kall, vall, q_);

    chunk_loop_kernel<<<pers_grid, 128, SMEM_BYTES>>>(
        kall, vall, a_, h_, e_, dh_, g2,
        W1, S1, W1tf, W2, S2, W2tf,
        a_t, l_t, dc_t, um, escale);

    ro1_kernel<<<dim3(H / 128, TOTROWS / 128), 256, BIG_SMEM_BYTES>>>(q_, W1tf, af_);
    ro2_kernel<<<dim3(D / 128, TOTROWS / 128), 256, BIG_SMEM_BYTES>>>(af_, W2tf, out);
}

// round 14
// speedup vs baseline: 1.0451x; 1.0451x over previous
#include <cuda_runtime.h>
#include <math.h>
#include <stdint.h>

#define D      512
#define H      1024
#define SEQ    4096
#define BATCH  4
#define CHUNK  256
#define NCHUNK 16
#define NROWS  (BATCH * CHUNK)   // 1024 rows per chunk step
#define TOTROWS (BATCH * SEQ)    // 16384 rows total

// ---- chunk GEMM core: 64x64x32, 128 thr, 4 stages ----
#define STAGES    4
#define STG_ELEMS 2304                            // 64*36 == 32*72
#define SMEM_BYTES (STAGES * 2 * STG_ELEMS * 4)   // 73728

// ---- big GEMM core: 128x128x32, 256 thr, 3 stages ----
#define BSTAGES   3
#define BIG_A_ELE (128 * 36)                      // 4608
#define BIG_B_ELE (32 * 136)                      // 4352
#define BIG_SMEM_BYTES (BSTAGES * (BIG_A_ELE + BIG_B_ELE) * 4)   // 107520

// ---------------- scratch ---------------------------------------------------------
__device__ float g_W1[D * H];          // fp32 master
__device__ float g_W2[H * D];
__device__ float g_W1tf[D * H];        // tf32 shadow (GEMM operand)
__device__ float g_W2tf[H * D];
__device__ float g_S1[D * H];
__device__ float g_S2[H * D];
__device__ float g_g2[H * D];
__device__ float g_xtf [TOTROWS * D];
__device__ float g_wktf[D * D];
__device__ float g_wvtf[D * D];
__device__ float g_wqtf[D * D];
__device__ float g_kall[TOTROWS * D];  // tf32 bits
__device__ float g_vall[TOTROWS * D];  // fp32 (epilogue aux, read-only in loop)
__device__ float g_q   [TOTROWS * D];  // tf32 bits
__device__ float g_h [NROWS * H];      // fp32 (dgelu aux, reused per chunk -> L2-only reads)
__device__ float g_a [NROWS * H];      // tf32 bits
__device__ float g_e [NROWS * D];      // tf32 bits
__device__ float g_dh[NROWS * H];      // tf32 bits
__device__ float g_af[TOTROWS * H];    // tf32 bits
__device__ unsigned g_bar[2];          // [0]=count, [1]=generation

// ---------------- helpers ---------------------------------------------------------
__device__ __forceinline__ float gelu_exact(float x) {
    return 0.5f * x * (1.0f + erff(x * 0.70710678118654752f));
}
__device__ __forceinline__ float dgelu_exact(float x) {
    return 0.5f * (1.0f + erff(x * 0.70710678118654752f))
         + x * 0.39894228040143268f * expf(-0.5f * x * x);
}
__device__ __forceinline__ uint32_t f2tf(float x) {
    uint32_t u;
    asm("cvt.rna.tf32.f32 %0, %1;" : "=r"(u) : "f"(x));
    return u;
}
__device__ __forceinline__ float f2tff(float x) { return __uint_as_float(f2tf(x)); }
__device__ __forceinline__ float sigm(float x) { return 1.0f / (1.0f + expf(-x)); }
__device__ __forceinline__ int chunk_map(int row, int t) {
    return (row >> 8) * SEQ + t * CHUNK + (row & 255);
}
__device__ __forceinline__ void cp16(uint32_t dst, const void* src) {
    asm volatile("cp.async.cg.shared.global [%0], [%1], 16;" :: "r"(dst), "l"(src));
}
__device__ __forceinline__ void cp_commit() {
    asm volatile("cp.async.commit_group;");
}
template <int N>
__device__ __forceinline__ void cp_wait() {
    asm volatile("cp.async.wait_group %0;" :: "n"(N));
}
__device__ __forceinline__ void mma_tf32(float c[4], const uint32_t a[4], const uint32_t b[2]) {
    asm volatile(
        "mma.sync.aligned.m16n8k8.row.col.f32.tf32.tf32.f32 "
        "{%0,%1,%2,%3}, {%4,%5,%6,%7}, {%8,%9}, {%0,%1,%2,%3};"
        : "+f"(c[0]), "+f"(c[1]), "+f"(c[2]), "+f"(c[3])
        : "r"(a[0]), "r"(a[1]), "r"(a[2]), "r"(a[3]), "r"(b[0]), "r"(b[1]));
}

// grid-wide barrier for persistent kernel.
// Writer side: release __threadfence before arrive (prior STGs visible at L2).
// Reader side: NO gpu-scope fence (that emits CCTL.IVALL = full L1D flush).
// Correct because all cross-CTA, cross-phase data is read L2-only:
// GEMM operands via cp.async.cg, h/g2 via __ldcg, spin via volatile.
// Remaining L1-cached traffic (vall/kall read-only; S/W CTA-private by the
// chunk-invariant tile->blockIdx map) cannot be stale.
__device__ __forceinline__ void grid_sync() {
    __syncthreads();
    if (threadIdx.x == 0) {
        unsigned gen = *(volatile unsigned*)&g_bar[1];
        __threadfence();                               // release
        if (atomicAdd(&g_bar[0], 1u) == gridDim.x - 1) {
            g_bar[0] = 0;
            __threadfence();
            *(volatile unsigned*)&g_bar[1] = gen + 1;
        } else {
            while (*(volatile unsigned*)&g_bar[1] == gen) { __nanosleep(64); }
        }
        __threadfence_block();                         // order spin before later ops
    }
    __syncthreads();
}

#define EPI_NONE     0
#define EPI_GELU_H   1   // aux2 = fp32 preact; C = tf32(gelu)
#define EPI_SUBSCALE 2   // C = tf32((AB - aux)*scale)
#define EPI_DGELU    3   // C = tf32(AB * dgelu(aux))   (aux read L2-only)
#define EPI_GRADUP   5   // fused S/W update + tf32 shadow

// ======== chunk GEMM core (64x64x32): operands are tf32 bits ====================
template <bool TA, bool TB, int EPI, bool CHUNKA, bool CHUNKAUX>
__device__ __forceinline__ void gemm_device(
    const float* __restrict__ A, const float* __restrict__ B, float* __restrict__ C,
    int M, int N, int K,
    const float* __restrict__ aux, float* __restrict__ aux2,
    float scale, int chunk_t, int bx, int by,
    float* __restrict__ W, float* __restrict__ S, float* __restrict__ Wtf,
    float alpha, float lr, float decay) {

    extern __shared__ float smem[];
    float* AsBase = smem;
    float* BsBase = smem + STAGES * STG_ELEMS;

    const int tid  = threadIdx.x;
    const int lane = tid & 31;
    const int warp = tid >> 5;
    const int g  = lane >> 2;
    const int tg = lane & 3;
    const int wm = warp >> 1;
    const int wn = warp & 1;
    const int bm = by * 64;
    const int bn = bx * 64;

    const float* pA[4]; int a_kk[4]; int a_sm[4];
    const float* pB[4]; int b_sm[4];
#pragma unroll
    for (int i = 0; i < 4; ++i) {
        int idx = tid + i * 128;
        if (!TA) {
            int row = idx >> 3, c4 = (idx & 7) * 4;
            int grow = bm + row;
            if (CHUNKA) grow = chunk_map(grow, chunk_t);
            pA[i]   = A + (size_t)grow * K + c4;
            a_sm[i] = row * 36 + c4;
            a_kk[i] = 0;
        } else {
            int kk = idx >> 4, m4 = (idx & 15) * 4;
            a_kk[i] = kk;
            pA[i]   = A + bm + m4;
            a_sm[i] = kk * 72 + m4;
        }
        if (!TB) {
            int kb = idx >> 4, n4 = (idx & 15) * 4;
            pB[i]   = B + (size_t)kb * N + bn + n4;
            b_sm[i] = kb * 72 + n4;
        } else {
            int n = idx >> 3, c4 = (idx & 7) * 4;
            pB[i]   = B + (size_t)(bn + n) * K + c4;
            b_sm[i] = n * 36 + c4;
        }
    }

    const uint32_t as_u0 = (uint32_t)__cvta_generic_to_shared(AsBase);
    const uint32_t bs_u0 = (uint32_t)__cvta_generic_to_shared(BsBase);

    auto load_stage = [&](int t8) {
        int s = t8 & (STAGES - 1);
        uint32_t as_u = as_u0 + (uint32_t)(s * STG_ELEMS * 4);
        uint32_t bs_u = bs_u0 + (uint32_t)(s * STG_ELEMS * 4);
        int k0 = t8 << 5;
#pragma unroll
        for (int i = 0; i < 4; ++i) {
            if (!TA) {
                cp16(as_u + a_sm[i] * 4, pA[i] + k0);
            } else {
                int row = k0 + a_kk[i];
                if (CHUNKA) row = chunk_map(row, chunk_t);
                cp16(as_u + a_sm[i] * 4, pA[i] + (size_t)row * M);
            }
        }
#pragma unroll
        for (int i = 0; i < 4; ++i) {
            if (!TB) cp16(bs_u + b_sm[i] * 4, pB[i] + (size_t)k0 * N);
            else     cp16(bs_u + b_sm[i] * 4, pB[i] + k0);
        }
        cp_commit();
    };

    float c[2][4][4] = {};
    auto mmas = [&](int t8) {
        int s = t8 & (STAGES - 1);
        const uint32_t* as = (const uint32_t*)(AsBase + s * STG_ELEMS);
        const uint32_t* bs = (const uint32_t*)(BsBase + s * STG_ELEMS);
#pragma unroll
        for (int kk = 0; kk < 32; kk += 8) {
            uint32_t af[2][4], bf[4][2];
#pragma unroll
            for (int mt = 0; mt < 2; ++mt) {
                int r0 = wm * 32 + mt * 16;
                if (!TA) {
                    af[mt][0] = as[(r0 + g)     * 36 + kk + tg];
                    af[mt][1] = as[(r0 + g + 8) * 36 + kk + tg];
                    af[mt][2] = as[(r0 + g)     * 36 + kk + tg + 4];
                    af[mt][3] = as[(r0 + g + 8) * 36 + kk + tg + 4];
                } else {
                    af[mt][0] = as[(kk + tg)     * 72 + r0 + g];
                    af[mt][1] = as[(kk + tg)     * 72 + r0 + g + 8];
                    af[mt][2] = as[(kk + tg + 4) * 72 + r0 + g];
                    af[mt][3] = as[(kk + tg + 4) * 72 + r0 + g + 8];
                }
            }
#pragma unroll
            for (int nt = 0; nt < 4; ++nt) {
                int cn = wn * 32 + nt * 8 + g;
                if (!TB) {
                    bf[nt][0] = bs[(kk + tg)     * 72 + cn];
                    bf[nt][1] = bs[(kk + tg + 4) * 72 + cn];
                } else {
                    bf[nt][0] = bs[cn * 36 + kk + tg];
                    bf[nt][1] = bs[cn * 36 + kk + tg + 4];
                }
            }
#pragma unroll
            for (int mt = 0; mt < 2; ++mt)
#pragma unroll
                for (int nt = 0; nt < 4; ++nt)
                    mma_tf32(c[mt][nt], af[mt], bf[nt]);
        }
    };

    const int nK = K >> 5;
#pragma unroll
    for (int s = 0; s < STAGES - 1; ++s) load_stage(s);
    for (int t8 = 0; t8 < nK; ++t8) {
        cp_wait<STAGES - 2>();
        __syncthreads();
        if (t8 + STAGES - 1 < nK) load_stage(t8 + STAGES - 1);
        else cp_commit();
        mmas(t8);
    }

#pragma unroll
    for (int mt = 0; mt < 2; ++mt) {
#pragma unroll
        for (int nt = 0; nt < 4; ++nt) {
#pragma unroll
            for (int half = 0; half < 2; ++half) {
                int row = bm + wm * 32 + mt * 16 + g + half * 8;
                int col = bn + wn * 32 + nt * 8 + 2 * tg;
                size_t cidx = (size_t)row * N + col;
                float v0 = c[mt][nt][half * 2 + 0];
                float v1 = c[mt][nt][half * 2 + 1];
                if (EPI == EPI_NONE) {
                    *(float2*)(C + cidx) = make_float2(v0, v1);
                } else if (EPI == EPI_GELU_H) {
                    *(float2*)(aux2 + cidx) = make_float2(v0, v1);
                    *(float2*)(C + cidx) = make_float2(f2tff(gelu_exact(v0)), f2tff(gelu_exact(v1)));
                } else if (EPI == EPI_SUBSCALE) {
                    size_t aidx = CHUNKAUX ? (size_t)chunk_map(row, chunk_t) * N + col : cidx;
                    float2 a2 = *(const float2*)(aux + aidx);   // vall: read-only, L1-safe
                    *(float2*)(C + cidx) = make_float2(f2tff((v0 - a2.x) * scale),
                                                       f2tff((v1 - a2.y) * scale));
                } else if (EPI == EPI_DGELU) {
                    float2 a2 = __ldcg((const float2*)(aux + cidx));   // h: L2-only (reused buffer)
                    *(float2*)(C + cidx) = make_float2(f2tff(v0 * dgelu_exact(a2.x)),
                                                       f2tff(v1 * dgelu_exact(a2.y)));
                } else if (EPI == EPI_GRADUP) {
                    float2 Sv = *(const float2*)(S + cidx);     // CTA-private across chunks
                    float2 Wv = *(const float2*)(W + cidx);
                    float s0 = decay * Sv.x - lr * v0;
                    float s1 = decay * Sv.y - lr * v1;
                    float w0 = (1.0f - alpha) * Wv.x + s0;
                    float w1 = (1.0f - alpha) * Wv.y + s1;
                    *(float2*)(S + cidx)   = make_float2(s0, s1);
                    *(float2*)(W + cidx)   = make_float2(w0, w1);
                    *(float2*)(Wtf + cidx) = make_float2(f2tff(w0), f2tff(w1));
                }
            }
        }
    }
}

// ======== persistent chunk-loop kernel ==========================================
__global__ void __launch_bounds__(128) chunk_loop_kernel(
    const float* __restrict__ kall, const float* __restrict__ vall,
    float* __restrict__ a, float* __restrict__ h,
    float* __restrict__ e, float* __restrict__ dh, float* __restrict__ g2,
    float* __restrict__ W1, float* __restrict__ S1, float* __restrict__ W1tf,
    float* __restrict__ W2, float* __restrict__ S2, float* __restrict__ W2tf,
    const float* __restrict__ sa, const float* __restrict__ sl,
    const float* __restrict__ sd, const int* __restrict__ um, float escale) {

    if (*um == 0) return;       // reference skips the whole recurrence
    const float alpha = sigm(*sa);
    const float lr    = sigm(*sl);
    const float decay = sigm(*sd);

    for (int t = 0; t < NCHUNK; ++t) {
        // P1: a,h = gelu/pre(k_chunk @ W1)    [16 x 16] = 256 tiles
        for (int tile = blockIdx.x; tile < 256; tile += gridDim.x)
            gemm_device<false, false, EPI_GELU_H, true, false>(
                kall, W1tf, a, NROWS, H, D, nullptr, h, 0.f, t,
                tile & 15, tile >> 4, nullptr, nullptr, nullptr, 0.f, 0.f, 0.f);
        grid_sync();
        // P2: e = tf32((a @ W2 - v_chunk)*escale)   [8 x 16] = 128 tiles
        for (int tile = blockIdx.x; tile < 128; tile += gridDim.x)
            gemm_device<false, false, EPI_SUBSCALE, false, true>(
                a, W2tf, e, NROWS, D, H, vall, nullptr, escale, t,
                tile & 7, tile >> 3, nullptr, nullptr, nullptr, 0.f, 0.f, 0.f);
        grid_sync();
        // P3: dh = tf32((e @ W2^T)*dgelu(h)) [256 tiles] ; g2 = a^T @ e [128 tiles]
        for (int tile = blockIdx.x; tile < 384; tile += gridDim.x) {
            if (tile < 256)
                gemm_device<false, true, EPI_DGELU, false, false>(
                    e, W2tf, dh, NROWS, H, D, h, nullptr, 0.f, 0,
                    tile & 15, tile >> 4, nullptr, nullptr, nullptr, 0.f, 0.f, 0.f);
            else {
                int t2 = tile - 256;
                gemm_device<true, false, EPI_NONE, false, false>(
                    a, e, g2, H, D, NROWS, nullptr, nullptr, 0.f, 0,
                    t2 & 7, t2 >> 3, nullptr, nullptr, nullptr, 0.f, 0.f, 0.f);
            }
        }
        grid_sync();
        // P4: g1 = k_chunk^T @ dh (fused W1/S1 update) [128] ; W2/S2 apply from g2 [128]
        for (int tile = blockIdx.x; tile < 256; tile += gridDim.x) {
            if (tile < 128) {
                gemm_device<true, false, EPI_GRADUP, true, false>(
                    kall, dh, nullptr, D, H, NROWS, nullptr, nullptr, 0.f, t,
                    tile & 15, tile >> 4, W1, S1, W1tf, alpha, lr, decay);
            } else {
                int base = (tile - 128) * 1024 + threadIdx.x;   // float4 index
#pragma unroll
                for (int j = 0; j < 8; ++j) {
                    int f4 = base + j * 128;
                    float4 gv = __ldcg(((const float4*)g2) + f4);   // g2: L2-only (reused buffer)
                    float4 Sv = ((const float4*)S2)[f4];            // CTA-private across chunks
                    float4 Wv = ((const float4*)W2)[f4];
                    Sv.x = decay * Sv.x - lr * gv.x;  Sv.y = decay * Sv.y - lr * gv.y;
                    Sv.z = decay * Sv.z - lr * gv.z;  Sv.w = decay * Sv.w - lr * gv.w;
                    Wv.x = (1.0f - alpha) * Wv.x + Sv.x;  Wv.y = (1.0f - alpha) * Wv.y + Sv.y;
                    Wv.z = (1.0f - alpha) * Wv.z + Sv.z;  Wv.w = (1.0f - alpha) * Wv.w + Sv.w;
                    ((float4*)S2)[f4] = Sv;
                    ((float4*)W2)[f4] = Wv;
                    ((float4*)W2tf)[f4] = make_float4(f2tff(Wv.x), f2tff(Wv.y),
                                                      f2tff(Wv.z), f2tff(Wv.w));
                }
            }
        }
        grid_sync();
    }
}

// ======== big GEMM core (128x128x32, 256 thr, warp tile 32x64) ==================
template <int EPIB>   // 0 = fp32 store, 1 = tf32 bits, 2 = tf32(gelu)
__device__ __forceinline__ void gemm_big(
    const float* __restrict__ A, const float* __restrict__ B, float* __restrict__ C,
    int N, int K, int bx, int by) {

    extern __shared__ float smem[];
    float* AsBase = smem;
    float* BsBase = smem + BSTAGES * BIG_A_ELE;

    const int tid  = threadIdx.x;
    const int lane = tid & 31;
    const int warp = tid >> 5;
    const int g  = lane >> 2;
    const int tg = lane & 3;
    const int wm = warp >> 1;
    const int wn = warp & 1;
    const int bm = by * 128;
    const int bn = bx * 128;

    const float* pA[4]; int a_sm[4];
    const float* pB[4]; int b_sm[4];
#pragma unroll
    for (int i = 0; i < 4; ++i) {
        int idx = tid + i * 256;
        int row = idx >> 3, c4 = (idx & 7) * 4;
        pA[i]   = A + (size_t)(bm + row) * K + c4;
        a_sm[i] = row * 36 + c4;
        int kb = idx >> 5, n4 = (idx & 31) * 4;
        pB[i]   = B + (size_t)kb * N + bn + n4;
        b_sm[i] = kb * 136 + n4;
    }

    const uint32_t as_u0 = (uint32_t)__cvta_generic_to_shared(AsBase);
    const uint32_t bs_u0 = (uint32_t)__cvta_generic_to_shared(BsBase);

    auto load_stage = [&](int t8, int s) {
        uint32_t as_u = as_u0 + (uint32_t)(s * BIG_A_ELE * 4);
        uint32_t bs_u = bs_u0 + (uint32_t)(s * BIG_B_ELE * 4);
        int k0 = t8 << 5;
#pragma unroll
        for (int i = 0; i < 4; ++i) cp16(as_u + a_sm[i] * 4, pA[i] + k0);
#pragma unroll
        for (int i = 0; i < 4; ++i) cp16(bs_u + b_sm[i] * 4, pB[i] + (size_t)k0 * N);
        cp_commit();
    };

    float c[2][8][4] = {};
    auto mmas = [&](int s) {
        const uint32_t* as = (const uint32_t*)(AsBase + s * BIG_A_ELE);
        const uint32_t* bs = (const uint32_t*)(BsBase + s * BIG_B_ELE);
#pragma unroll
        for (int kk = 0; kk < 32; kk += 8) {
            uint32_t af[2][4], bf[8][2];
#pragma unroll
            for (int mt = 0; mt < 2; ++mt) {
                int r0 = wm * 32 + mt * 16;
                af[mt][0] = as[(r0 + g)     * 36 + kk + tg];
                af[mt][1] = as[(r0 + g + 8) * 36 + kk + tg];
                af[mt][2] = as[(r0 + g)     * 36 + kk + tg + 4];
                af[mt][3] = as[(r0 + g + 8) * 36 + kk + tg + 4];
            }
#pragma unroll
            for (int nt = 0; nt < 8; ++nt) {
                int cn = wn * 64 + nt * 8 + g;
                bf[nt][0] = bs[(kk + tg)     * 136 + cn];
                bf[nt][1] = bs[(kk + tg + 4) * 136 + cn];
            }
#pragma unroll
            for (int mt = 0; mt < 2; ++mt)
#pragma unroll
                for (int nt = 0; nt < 8; ++nt)
                    mma_tf32(c[mt][nt], af[mt], bf[nt]);
        }
    };

    const int nK = K >> 5;
    load_stage(0, 0);
    load_stage(1, 1);
    for (int t8 = 0; t8 < nK; ++t8) {
        cp_wait<BSTAGES - 2>();
        __syncthreads();
        int nxt = t8 + BSTAGES - 1;
        if (nxt < nK) load_stage(nxt, nxt % BSTAGES);
        else cp_commit();
        mmas(t8 % BSTAGES);
    }

#pragma unroll
    for (int mt = 0; mt < 2; ++mt) {
#pragma unroll
        for (int nt = 0; nt < 8; ++nt) {
#pragma unroll
            for (int half = 0; half < 2; ++half) {
                int row = bm + wm * 32 + mt * 16 + g + half * 8;
                int col = bn + wn * 64 + nt * 8 + 2 * tg;
                size_t cidx = (size_t)row * N + col;
                float v0 = c[mt][nt][half * 2 + 0];
                float v1 = c[mt][nt][half * 2 + 1];
                if (EPIB == 0)      *(float2*)(C + cidx) = make_float2(v0, v1);
                else if (EPIB == 1) *(float2*)(C + cidx) = make_float2(f2tff(v0), f2tff(v1));
                else                *(float2*)(C + cidx) = make_float2(f2tff(gelu_exact(v0)),
                                                                      f2tff(gelu_exact(v1)));
            }
        }
    }
}

// ======== global kernels ========================================================
#define X4   (TOTROWS * D / 4)    // 2097152
#define WW4  (D * D / 4)          // 65536
#define W14  (D * H / 4)          // 131072
#define CVT_TOTAL (X4 + 3 * WW4 + 2 * W14)   // 2555904

__global__ void __launch_bounds__(256) cvt_all_kernel(
    const float4* __restrict__ x, const float4* __restrict__ wk,
    const float4* __restrict__ wv, const float4* __restrict__ wq,
    const float4* __restrict__ w1, const float4* __restrict__ w2,
    float4* __restrict__ xo, float4* __restrict__ wko, float4* __restrict__ wvo,
    float4* __restrict__ wqo, float4* __restrict__ w1o, float4* __restrict__ w2o) {
    int i = blockIdx.x * blockDim.x + threadIdx.x;
    if (i >= CVT_TOTAL) return;
    const float4* src; float4* dst; int off;
    if (i < X4)                            { src = x;  dst = xo;  off = i; }
    else if (i < X4 + WW4)                 { src = wk; dst = wko; off = i - X4; }
    else if (i < X4 + 2 * WW4)             { src = wv; dst = wvo; off = i - X4 - WW4; }
    else if (i < X4 + 3 * WW4)             { src = wq; dst = wqo; off = i - X4 - 2 * WW4; }
    else if (i < X4 + 3 * WW4 + W14)       { src = w1; dst = w1o; off = i - X4 - 3 * WW4; }
    else                                   { src = w2; dst = w2o; off = i - X4 - 3 * WW4 - W14; }
    float4 v = src[off];
    dst[off] = make_float4(f2tff(v.x), f2tff(v.y), f2tff(v.z), f2tff(v.w));
}

__global__ void __launch_bounds__(256) proj_kernel(
    const float* __restrict__ xtf, const float* __restrict__ wktf,
    const float* __restrict__ wvtf, const float* __restrict__ wqtf,
    float* __restrict__ kall, float* __restrict__ vall, float* __restrict__ q) {
    if (blockIdx.z == 0)
        gemm_big<1>(xtf, wktf, kall, D, D, blockIdx.x, blockIdx.y);
    else if (blockIdx.z == 1)
        gemm_big<0>(xtf, wvtf, vall, D, D, blockIdx.x, blockIdx.y);
    else
        gemm_big<1>(xtf, wqtf, q, D, D, blockIdx.x, blockIdx.y);
}

__global__ void __launch_bounds__(256) ro1_kernel(
    const float* __restrict__ q, const float* __restrict__ W1tf, float* __restrict__ af) {
    gemm_big<2>(q, W1tf, af, H, D, blockIdx.x, blockIdx.y);
}
__global__ void __launch_bounds__(256) ro2_kernel(
    const float* __restrict__ af, const float* __restrict__ W2tf, float* __restrict__ out) {
    gemm_big<0>(af, W2tf, out, D, H, blockIdx.x, blockIdx.y);
}

// ---------------- launch ---------------------------------------------------------
extern "C" void kernel_launch(void* const* d_in, const int* in_sizes, int n_in,
                              void* d_out, int out_size) {
    const float* x    = (const float*)d_in[0];
    const float* w_q  = (const float*)d_in[1];
    const float* w_k  = (const float*)d_in[2];
    const float* w_v  = (const float*)d_in[3];
    const float* mw1  = (const float*)d_in[4];
    const float* mw2  = (const float*)d_in[5];
    const float* a_t  = (const float*)d_in[6];
    const float* l_t  = (const float*)d_in[7];
    const float* dc_t = (const float*)d_in[8];
    const int*   um   = (const int*)  d_in[9];
    float* out = (float*)d_out;

    static int pers_grid = 0;
    if (!pers_grid) {
        cudaFuncSetAttribute(proj_kernel, cudaFuncAttributeMaxDynamicSharedMemorySize, BIG_SMEM_BYTES);
        cudaFuncSetAttribute(ro1_kernel,  cudaFuncAttributeMaxDynamicSharedMemorySize, BIG_SMEM_BYTES);
        cudaFuncSetAttribute(ro2_kernel,  cudaFuncAttributeMaxDynamicSharedMemorySize, BIG_SMEM_BYTES);
        cudaFuncSetAttribute(chunk_loop_kernel, cudaFuncAttributeMaxDynamicSharedMemorySize, SMEM_BYTES);
        int per_sm = 0;
        cudaOccupancyMaxActiveBlocksPerMultiprocessor(&per_sm, chunk_loop_kernel, 128, SMEM_BYTES);
        if (per_sm < 1) per_sm = 1;
        int dev = 0, sms = 0;
        cudaGetDevice(&dev);
        cudaDeviceGetAttribute(&sms, cudaDevAttrMultiProcessorCount, dev);
        pers_grid = per_sm * sms;        // guaranteed co-resident
        if (pers_grid > 384) pers_grid = 384;   // max tiles in any phase
    }

    float *W1, *W2, *W1tf, *W2tf, *S1, *S2, *g2, *xtf, *wktf, *wvtf, *wqtf;
    float *kall, *vall, *q_, *h_, *a_, *e_, *dh_, *af_;
    unsigned* bar;
    cudaGetSymbolAddress((void**)&W1,   g_W1);
    cudaGetSymbolAddress((void**)&W2,   g_W2);
    cudaGetSymbolAddress((void**)&W1tf, g_W1tf);
    cudaGetSymbolAddress((void**)&W2tf, g_W2tf);
    cudaGetSymbolAddress((void**)&S1,   g_S1);
    cudaGetSymbolAddress((void**)&S2,   g_S2);
    cudaGetSymbolAddress((void**)&g2,   g_g2);
    cudaGetSymbolAddress((void**)&xtf,  g_xtf);
    cudaGetSymbolAddress((void**)&wktf, g_wktf);
    cudaGetSymbolAddress((void**)&wvtf, g_wvtf);
    cudaGetSymbolAddress((void**)&wqtf, g_wqtf);
    cudaGetSymbolAddress((void**)&kall, g_kall);
    cudaGetSymbolAddress((void**)&vall, g_vall);
    cudaGetSymbolAddress((void**)&q_,   g_q);
    cudaGetSymbolAddress((void**)&h_,   g_h);
    cudaGetSymbolAddress((void**)&a_,   g_a);
    cudaGetSymbolAddress((void**)&e_,   g_e);
    cudaGetSymbolAddress((void**)&dh_,  g_dh);
    cudaGetSymbolAddress((void**)&af_,  g_af);
    cudaGetSymbolAddress((void**)&bar,  g_bar);

    cudaMemcpyAsync(W1, mw1, sizeof(float) * D * H, cudaMemcpyDeviceToDevice);
    cudaMemcpyAsync(W2, mw2, sizeof(float) * H * D, cudaMemcpyDeviceToDevice);
    cudaMemsetAsync(S1, 0, sizeof(float) * D * H);
    cudaMemsetAsync(S2, 0, sizeof(float) * H * D);
    cudaMemsetAsync(bar, 0, 2 * sizeof(unsigned));

    cvt_all_kernel<<<(CVT_TOTAL + 255) / 256, 256>>>(
        (const float4*)x, (const float4*)w_k, (const float4*)w_v, (const float4*)w_q,
        (const float4*)mw1, (const float4*)mw2,
        (float4*)xtf, (float4*)wktf, (float4*)wvtf, (float4*)wqtf,
        (float4*)W1tf, (float4*)W2tf);

    const float escale = 2.0f / (float)(NROWS * D);

    proj_kernel<<<dim3(D / 128, TOTROWS / 128, 3), 256, BIG_SMEM_BYTES>>>(
        xtf, wktf, wvtf, wqtf, kall, vall, q_);

    chunk_loop_kernel<<<pers_grid, 128, SMEM_BYTES>>>(
        kall, vall, a_, h_, e_, dh_, g2,
        W1, S1, W1tf, W2, S2, W2tf,
        a_t, l_t, dc_t, um, escale);

    ro1_kernel<<<dim3(H / 128, TOTROWS / 128), 256, BIG_SMEM_BYTES>>>(q_, W1tf, af_);
    ro2_kernel<<<dim3(D / 128, TOTROWS / 128), 256, BIG_SMEM_BYTES>>>(af_, W2tf, out);
}

// round 16
// speedup vs baseline: 1.1447x; 1.0952x over previous
#include <cuda_runtime.h>
#include <math.h>
#include <stdint.h>

#define D      512
#define H      1024
#define SEQ    4096
#define BATCH  4
#define CHUNK  256
#define NCHUNK 16
#define NROWS  (BATCH * CHUNK)   // 1024 rows per chunk step
#define TOTROWS (BATCH * SEQ)    // 16384 rows total

// ---- chunk GEMM core: 64x64x32, 128 thr, 4 stages ----
#define STAGES    4
#define STG_ELEMS 2304                            // 64*36 == 32*72
#define SMEM_BYTES (STAGES * 2 * STG_ELEMS * 4)   // 73728

// ---- big GEMM core: 128x128x32, 256 thr, 3 stages ----
#define BSTAGES   3
#define BIG_A_ELE (128 * 36)                      // 4608
#define BIG_B_ELE (32 * 136)                      // 4352
#define BIG_SMEM_BYTES (BSTAGES * (BIG_A_ELE + BIG_B_ELE) * 4)   // 107520

// ---------------- scratch ---------------------------------------------------------
__device__ float g_W1[D * H];          // fp32 master
__device__ float g_W2[H * D];
__device__ float g_W1tf[D * H];        // tf32 shadow (GEMM operand)
__device__ float g_W2tf[H * D];
__device__ float g_S1[D * H];
__device__ float g_S2[H * D];
__device__ float g_g2[H * D];
__device__ float g_xtf [TOTROWS * D];
__device__ float g_wktf[D * D];
__device__ float g_wvtf[D * D];
__device__ float g_wqtf[D * D];
__device__ float g_kall[TOTROWS * D];  // tf32 bits
__device__ float g_vall[TOTROWS * D];  // fp32 (epilogue aux)
__device__ float g_q   [TOTROWS * D];  // tf32 bits
__device__ float g_h [NROWS * H];      // fp32 (dgelu aux)
__device__ float g_a [NROWS * H];      // tf32 bits
__device__ float g_e [NROWS * D];      // tf32 bits
__device__ float g_dh[NROWS * H];      // tf32 bits
__device__ float g_af[TOTROWS * H];    // tf32 bits

// ---------------- helpers ---------------------------------------------------------
__device__ __forceinline__ float gelu_exact(float x) {
    return 0.5f * x * (1.0f + erff(x * 0.70710678118654752f));
}
__device__ __forceinline__ float dgelu_exact(float x) {
    return 0.5f * (1.0f + erff(x * 0.70710678118654752f))
         + x * 0.39894228040143268f * expf(-0.5f * x * x);
}
__device__ __forceinline__ uint32_t f2tf(float x) {
    uint32_t u;
    asm("cvt.rna.tf32.f32 %0, %1;" : "=r"(u) : "f"(x));
    return u;
}
__device__ __forceinline__ float f2tff(float x) { return __uint_as_float(f2tf(x)); }
__device__ __forceinline__ float sigm(float x) { return 1.0f / (1.0f + expf(-x)); }
__device__ __forceinline__ int chunk_map(int row, int t) {
    return (row >> 8) * SEQ + t * CHUNK + (row & 255);
}
__device__ __forceinline__ void cp16(uint32_t dst, const void* src) {
    asm volatile("cp.async.cg.shared.global [%0], [%1], 16;" :: "r"(dst), "l"(src));
}
__device__ __forceinline__ void cp_commit() {
    asm volatile("cp.async.commit_group;");
}
template <int N>
__device__ __forceinline__ void cp_wait() {
    asm volatile("cp.async.wait_group %0;" :: "n"(N));
}
__device__ __forceinline__ void mma_tf32(float c[4], const uint32_t a[4], const uint32_t b[2]) {
    asm volatile(
        "mma.sync.aligned.m16n8k8.row.col.f32.tf32.tf32.f32 "
        "{%0,%1,%2,%3}, {%4,%5,%6,%7}, {%8,%9}, {%0,%1,%2,%3};"
        : "+f"(c[0]), "+f"(c[1]), "+f"(c[2]), "+f"(c[3])
        : "r"(a[0]), "r"(a[1]), "r"(a[2]), "r"(a[3]), "r"(b[0]), "r"(b[1]));
}

#define EPI_NONE     0
#define EPI_GELU_H   1   // aux2 = fp32 preact; C = tf32(gelu)
#define EPI_SUBSCALE 2   // C = tf32((AB - aux)*scale)
#define EPI_DGELU    3   // C = tf32(AB * dgelu(aux))
#define EPI_GRADUP   5   // fused S/W update + tf32 shadow

// ======== chunk GEMM core (64x64x32): operands are tf32 bits ====================
template <bool TA, bool TB, int EPI, bool CHUNKA, bool CHUNKAUX>
__device__ __forceinline__ void gemm_device(
    const float* __restrict__ A, const float* __restrict__ B, float* __restrict__ C,
    int M, int N, int K,
    const float* __restrict__ aux, float* __restrict__ aux2,
    float scale, int chunk_t, int bx, int by,
    float* __restrict__ W, float* __restrict__ S, float* __restrict__ Wtf,
    float alpha, float lr, float decay, int du) {

    extern __shared__ float smem[];
    float* AsBase = smem;
    float* BsBase = smem + STAGES * STG_ELEMS;

    const int tid  = threadIdx.x;
    const int lane = tid & 31;
    const int warp = tid >> 5;
    const int g  = lane >> 2;
    const int tg = lane & 3;
    const int wm = warp >> 1;
    const int wn = warp & 1;
    const int bm = by * 64;
    const int bn = bx * 64;

    const float* pA[4]; int a_kk[4]; int a_sm[4];
    const float* pB[4]; int b_sm[4];
#pragma unroll
    for (int i = 0; i < 4; ++i) {
        int idx = tid + i * 128;
        if (!TA) {
            int row = idx >> 3, c4 = (idx & 7) * 4;
            int grow = bm + row;
            if (CHUNKA) grow = chunk_map(grow, chunk_t);
            pA[i]   = A + (size_t)grow * K + c4;
            a_sm[i] = row * 36 + c4;
            a_kk[i] = 0;
        } else {
            int kk = idx >> 4, m4 = (idx & 15) * 4;
            a_kk[i] = kk;
            pA[i]   = A + bm + m4;
            a_sm[i] = kk * 72 + m4;
        }
        if (!TB) {
            int kb = idx >> 4, n4 = (idx & 15) * 4;
            pB[i]   = B + (size_t)kb * N + bn + n4;
            b_sm[i] = kb * 72 + n4;
        } else {
            int n = idx >> 3, c4 = (idx & 7) * 4;
            pB[i]   = B + (size_t)(bn + n) * K + c4;
            b_sm[i] = n * 36 + c4;
        }
    }

    const uint32_t as_u0 = (uint32_t)__cvta_generic_to_shared(AsBase);
    const uint32_t bs_u0 = (uint32_t)__cvta_generic_to_shared(BsBase);

    auto load_stage = [&](int t8) {
        int s = t8 & (STAGES - 1);
        uint32_t as_u = as_u0 + (uint32_t)(s * STG_ELEMS * 4);
        uint32_t bs_u = bs_u0 + (uint32_t)(s * STG_ELEMS * 4);
        int k0 = t8 << 5;
#pragma unroll
        for (int i = 0; i < 4; ++i) {
            if (!TA) {
                cp16(as_u + a_sm[i] * 4, pA[i] + k0);
            } else {
                int row = k0 + a_kk[i];
                if (CHUNKA) row = chunk_map(row, chunk_t);
                cp16(as_u + a_sm[i] * 4, pA[i] + (size_t)row * M);
            }
        }
#pragma unroll
        for (int i = 0; i < 4; ++i) {
            if (!TB) cp16(bs_u + b_sm[i] * 4, pB[i] + (size_t)k0 * N);
            else     cp16(bs_u + b_sm[i] * 4, pB[i] + k0);
        }
        cp_commit();
    };

    float c[2][4][4] = {};
    auto mmas = [&](int t8) {
        int s = t8 & (STAGES - 1);
        const uint32_t* as = (const uint32_t*)(AsBase + s * STG_ELEMS);
        const uint32_t* bs = (const uint32_t*)(BsBase + s * STG_ELEMS);
#pragma unroll
        for (int kk = 0; kk < 32; kk += 8) {
            uint32_t af[2][4], bf[4][2];
#pragma unroll
            for (int mt = 0; mt < 2; ++mt) {
                int r0 = wm * 32 + mt * 16;
                if (!TA) {
                    af[mt][0] = as[(r0 + g)     * 36 + kk + tg];
                    af[mt][1] = as[(r0 + g + 8) * 36 + kk + tg];
                    af[mt][2] = as[(r0 + g)     * 36 + kk + tg + 4];
                    af[mt][3] = as[(r0 + g + 8) * 36 + kk + tg + 4];
                } else {
                    af[mt][0] = as[(kk + tg)     * 72 + r0 + g];
                    af[mt][1] = as[(kk + tg)     * 72 + r0 + g + 8];
                    af[mt][2] = as[(kk + tg + 4) * 72 + r0 + g];
                    af[mt][3] = as[(kk + tg + 4) * 72 + r0 + g + 8];
                }
            }
#pragma unroll
            for (int nt = 0; nt < 4; ++nt) {
                int cn = wn * 32 + nt * 8 + g;
                if (!TB) {
                    bf[nt][0] = bs[(kk + tg)     * 72 + cn];
                    bf[nt][1] = bs[(kk + tg + 4) * 72 + cn];
                } else {
                    bf[nt][0] = bs[cn * 36 + kk + tg];
                    bf[nt][1] = bs[cn * 36 + kk + tg + 4];
                }
            }
#pragma unroll
            for (int mt = 0; mt < 2; ++mt)
#pragma unroll
                for (int nt = 0; nt < 4; ++nt)
                    mma_tf32(c[mt][nt], af[mt], bf[nt]);
        }
    };

    const int nK = K >> 5;
#pragma unroll
    for (int s = 0; s < STAGES - 1; ++s) load_stage(s);
    for (int t8 = 0; t8 < nK; ++t8) {
        cp_wait<STAGES - 2>();
        __syncthreads();
        if (t8 + STAGES - 1 < nK) load_stage(t8 + STAGES - 1);
        else cp_commit();
        mmas(t8);
    }

    if (EPI == EPI_GRADUP && !du) return;

#pragma unroll
    for (int mt = 0; mt < 2; ++mt) {
#pragma unroll
        for (int nt = 0; nt < 4; ++nt) {
#pragma unroll
            for (int half = 0; half < 2; ++half) {
                int row = bm + wm * 32 + mt * 16 + g + half * 8;
                int col = bn + wn * 32 + nt * 8 + 2 * tg;
                size_t cidx = (size_t)row * N + col;
                float v0 = c[mt][nt][half * 2 + 0];
                float v1 = c[mt][nt][half * 2 + 1];
                if (EPI == EPI_NONE) {
                    *(float2*)(C + cidx) = make_float2(v0, v1);
                } else if (EPI == EPI_GELU_H) {
                    *(float2*)(aux2 + cidx) = make_float2(v0, v1);
                    *(float2*)(C + cidx) = make_float2(f2tff(gelu_exact(v0)), f2tff(gelu_exact(v1)));
                } else if (EPI == EPI_SUBSCALE) {
                    size_t aidx = CHUNKAUX ? (size_t)chunk_map(row, chunk_t) * N + col : cidx;
                    float2 a2 = *(const float2*)(aux + aidx);
                    *(float2*)(C + cidx) = make_float2(f2tff((v0 - a2.x) * scale),
                                                       f2tff((v1 - a2.y) * scale));
                } else if (EPI == EPI_DGELU) {
                    float2 a2 = *(const float2*)(aux + cidx);
                    *(float2*)(C + cidx) = make_float2(f2tff(v0 * dgelu_exact(a2.x)),
                                                       f2tff(v1 * dgelu_exact(a2.y)));
                } else if (EPI == EPI_GRADUP) {
                    float2 Sv = *(const float2*)(S + cidx);
                    float2 Wv = *(const float2*)(W + cidx);
                    float s0 = decay * Sv.x - lr * v0;
                    float s1 = decay * Sv.y - lr * v1;
                    float w0 = (1.0f - alpha) * Wv.x + s0;
                    float w1 = (1.0f - alpha) * Wv.y + s1;
                    *(float2*)(S + cidx)   = make_float2(s0, s1);
                    *(float2*)(W + cidx)   = make_float2(w0, w1);
                    *(float2*)(Wtf + cidx) = make_float2(f2tff(w0), f2tff(w1));
                }
            }
        }
    }
}

// ======== big GEMM core (128x128x32, 256 thr, warp tile 32x64) ==================
template <int EPIB>   // 0 = fp32 store, 1 = tf32 bits, 2 = tf32(gelu)
__device__ __forceinline__ void gemm_big(
    const float* __restrict__ A, const float* __restrict__ B, float* __restrict__ C,
    int N, int K, int bx, int by) {

    extern __shared__ float smem[];
    float* AsBase = smem;
    float* BsBase = smem + BSTAGES * BIG_A_ELE;

    const int tid  = threadIdx.x;
    const int lane = tid & 31;
    const int warp = tid >> 5;
    const int g  = lane >> 2;
    const int tg = lane & 3;
    const int wm = warp >> 1;
    const int wn = warp & 1;
    const int bm = by * 128;
    const int bn = bx * 128;

    const float* pA[4]; int a_sm[4];
    const float* pB[4]; int b_sm[4];
#pragma unroll
    for (int i = 0; i < 4; ++i) {
        int idx = tid + i * 256;
        int row = idx >> 3, c4 = (idx & 7) * 4;
        pA[i]   = A + (size_t)(bm + row) * K + c4;
        a_sm[i] = row * 36 + c4;
        int kb = idx >> 5, n4 = (idx & 31) * 4;
        pB[i]   = B + (size_t)kb * N + bn + n4;
        b_sm[i] = kb * 136 + n4;
    }

    const uint32_t as_u0 = (uint32_t)__cvta_generic_to_shared(AsBase);
    const uint32_t bs_u0 = (uint32_t)__cvta_generic_to_shared(BsBase);

    auto load_stage = [&](int t8, int s) {
        uint32_t as_u = as_u0 + (uint32_t)(s * BIG_A_ELE * 4);
        uint32_t bs_u = bs_u0 + (uint32_t)(s * BIG_B_ELE * 4);
        int k0 = t8 << 5;
#pragma unroll
        for (int i = 0; i < 4; ++i) cp16(as_u + a_sm[i] * 4, pA[i] + k0);
#pragma unroll
        for (int i = 0; i < 4; ++i) cp16(bs_u + b_sm[i] * 4, pB[i] + (size_t)k0 * N);
        cp_commit();
    };

    float c[2][8][4] = {};
    auto mmas = [&](int s) {
        const uint32_t* as = (const uint32_t*)(AsBase + s * BIG_A_ELE);
        const uint32_t* bs = (const uint32_t*)(BsBase + s * BIG_B_ELE);
#pragma unroll
        for (int kk = 0; kk < 32; kk += 8) {
            uint32_t af[2][4], bf[8][2];
#pragma unroll
            for (int mt = 0; mt < 2; ++mt) {
                int r0 = wm * 32 + mt * 16;
                af[mt][0] = as[(r0 + g)     * 36 + kk + tg];
                af[mt][1] = as[(r0 + g + 8) * 36 + kk + tg];
                af[mt][2] = as[(r0 + g)     * 36 + kk + tg + 4];
                af[mt][3] = as[(r0 + g + 8) * 36 + kk + tg + 4];
            }
#pragma unroll
            for (int nt = 0; nt < 8; ++nt) {
                int cn = wn * 64 + nt * 8 + g;
                bf[nt][0] = bs[(kk + tg)     * 136 + cn];
                bf[nt][1] = bs[(kk + tg + 4) * 136 + cn];
            }
#pragma unroll
            for (int mt = 0; mt < 2; ++mt)
#pragma unroll
                for (int nt = 0; nt < 8; ++nt)
                    mma_tf32(c[mt][nt], af[mt], bf[nt]);
        }
    };

    const int nK = K >> 5;
    load_stage(0, 0);
    load_stage(1, 1);
    for (int t8 = 0; t8 < nK; ++t8) {
        cp_wait<BSTAGES - 2>();
        __syncthreads();
        int nxt = t8 + BSTAGES - 1;
        if (nxt < nK) load_stage(nxt, nxt % BSTAGES);
        else cp_commit();
        mmas(t8 % BSTAGES);
    }

#pragma unroll
    for (int mt = 0; mt < 2; ++mt) {
#pragma unroll
        for (int nt = 0; nt < 8; ++nt) {
#pragma unroll
            for (int half = 0; half < 2; ++half) {
                int row = bm + wm * 32 + mt * 16 + g + half * 8;
                int col = bn + wn * 64 + nt * 8 + 2 * tg;
                size_t cidx = (size_t)row * N + col;
                float v0 = c[mt][nt][half * 2 + 0];
                float v1 = c[mt][nt][half * 2 + 1];
                if (EPIB == 0)      *(float2*)(C + cidx) = make_float2(v0, v1);
                else if (EPIB == 1) *(float2*)(C + cidx) = make_float2(f2tff(v0), f2tff(v1));
                else                *(float2*)(C + cidx) = make_float2(f2tff(gelu_exact(v0)),
                                                                      f2tff(gelu_exact(v1)));
            }
        }
    }
}

// ======== global kernels ========================================================
#define X4   (TOTROWS * D / 4)    // 2097152
#define WW4  (D * D / 4)          // 65536
#define W14  (D * H / 4)          // 131072
#define CVT_TOTAL (X4 + 3 * WW4 + 2 * W14)   // 2555904

__global__ void __launch_bounds__(256) cvt_all_kernel(
    const float4* __restrict__ x, const float4* __restrict__ wk,
    const float4* __restrict__ wv, const float4* __restrict__ wq,
    const float4* __restrict__ w1, const float4* __restrict__ w2,
    float4* __restrict__ xo, float4* __restrict__ wko, float4* __restrict__ wvo,
    float4* __restrict__ wqo, float4* __restrict__ w1o, float4* __restrict__ w2o) {
    int i = blockIdx.x * blockDim.x + threadIdx.x;
    if (i >= CVT_TOTAL) return;
    const float4* src; float4* dst; int off;
    if (i < X4)                            { src = x;  dst = xo;  off = i; }
    else if (i < X4 + WW4)                 { src = wk; dst = wko; off = i - X4; }
    else if (i < X4 + 2 * WW4)             { src = wv; dst = wvo; off = i - X4 - WW4; }
    else if (i < X4 + 3 * WW4)             { src = wq; dst = wqo; off = i - X4 - 2 * WW4; }
    else if (i < X4 + 3 * WW4 + W14)       { src = w1; dst = w1o; off = i - X4 - 3 * WW4; }
    else                                   { src = w2; dst = w2o; off = i - X4 - 3 * WW4 - W14; }
    float4 v = src[off];
    dst[off] = make_float4(f2tff(v.x), f2tff(v.y), f2tff(v.z), f2tff(v.w));
}

__global__ void __launch_bounds__(256) proj_kernel(
    const float* __restrict__ xtf, const float* __restrict__ wktf,
    const float* __restrict__ wvtf, const float* __restrict__ wqtf,
    float* __restrict__ kall, float* __restrict__ vall, float* __restrict__ q) {
    if (blockIdx.z == 0)
        gemm_big<1>(xtf, wktf, kall, D, D, blockIdx.x, blockIdx.y);
    else if (blockIdx.z == 1)
        gemm_big<0>(xtf, wvtf, vall, D, D, blockIdx.x, blockIdx.y);
    else
        gemm_big<1>(xtf, wqtf, q, D, D, blockIdx.x, blockIdx.y);
}

__global__ void __launch_bounds__(128) h_kernel(
    const float* __restrict__ kall, const float* __restrict__ W1tf,
    float* __restrict__ a, float* __restrict__ h, int t) {
    gemm_device<false, false, EPI_GELU_H, true, false>(
        kall, W1tf, a, NROWS, H, D, nullptr, h, 0.f, t, blockIdx.x, blockIdx.y,
        nullptr, nullptr, nullptr, 0.f, 0.f, 0.f, 0);
}

__global__ void __launch_bounds__(128) e_kernel(
    const float* __restrict__ a, const float* __restrict__ W2tf,
    float* __restrict__ e, const float* __restrict__ vall, float scale, int t) {
    gemm_device<false, false, EPI_SUBSCALE, false, true>(
        a, W2tf, e, NROWS, D, H, vall, nullptr, scale, t, blockIdx.x, blockIdx.y,
        nullptr, nullptr, nullptr, 0.f, 0.f, 0.f, 0);
}

// critical path: dh = tf32((e @ W2^T) * dgelu(h))   [16 x 16] tiles
__global__ void __launch_bounds__(128) dh_kernel(
    const float* __restrict__ e, const float* __restrict__ W2tf,
    float* __restrict__ dh, const float* __restrict__ h) {
    gemm_device<false, true, EPI_DGELU, false, false>(
        e, W2tf, dh, NROWS, H, D, h, nullptr, 0.f, 0, blockIdx.x, blockIdx.y,
        nullptr, nullptr, nullptr, 0.f, 0.f, 0.f, 0);
}

// off-path (stream1): g2 = a^T @ e   [8 x 16] tiles
__global__ void __launch_bounds__(128) g2_kernel(
    const float* __restrict__ a, const float* __restrict__ e, float* __restrict__ g2) {
    gemm_device<true, false, EPI_NONE, false, false>(
        a, e, g2, H, D, NROWS, nullptr, nullptr, 0.f, 0, blockIdx.x, blockIdx.y,
        nullptr, nullptr, nullptr, 0.f, 0.f, 0.f, 0);
}

// critical path: g1 = k_chunk^T @ dh with fused W1/S1 update   [16 x 8] tiles
__global__ void __launch_bounds__(128) g1upd_kernel(
    const float* __restrict__ kall, const float* __restrict__ dh,
    float* __restrict__ W1, float* __restrict__ S1, float* __restrict__ W1tf,
    const float* __restrict__ sa, const float* __restrict__ sl,
    const float* __restrict__ sd, const int* __restrict__ um, int t) {
    const int du = *um;
    float alpha = 0.f, lr = 0.f, decay = 0.f;
    if (du) { alpha = sigm(*sa); lr = sigm(*sl); decay = sigm(*sd); }
    gemm_device<true, false, EPI_GRADUP, true, false>(
        kall, dh, nullptr, D, H, NROWS, nullptr, nullptr, 0.f, t,
        blockIdx.x, blockIdx.y, W1, S1, W1tf, alpha, lr, decay, du);
}

// off-path (stream1, after dh): elementwise W2/S2 apply from g2 buffer
__global__ void __launch_bounds__(256) w2upd_kernel(
    float* __restrict__ W2, float* __restrict__ S2, float* __restrict__ W2tf,
    const float* __restrict__ g2,
    const float* __restrict__ sa, const float* __restrict__ sl,
    const float* __restrict__ sd, const int* __restrict__ um) {
    if (*um == 0) return;
    const float alpha = sigm(*sa);
    const float lr    = sigm(*sl);
    const float decay = sigm(*sd);
    int base = blockIdx.x * 1024 + threadIdx.x;   // float4 index; grid 128 x 256thr x 4
#pragma unroll
    for (int j = 0; j < 4; ++j) {
        int f4 = base + j * 256;
        float4 gv = ((const float4*)g2)[f4];
        float4 Sv = ((const float4*)S2)[f4];
        float4 Wv = ((const float4*)W2)[f4];
        Sv.x = decay * Sv.x - lr * gv.x;  Sv.y = decay * Sv.y - lr * gv.y;
        Sv.z = decay * Sv.z - lr * gv.z;  Sv.w = decay * Sv.w - lr * gv.w;
        Wv.x = (1.0f - alpha) * Wv.x + Sv.x;  Wv.y = (1.0f - alpha) * Wv.y + Sv.y;
        Wv.z = (1.0f - alpha) * Wv.z + Sv.z;  Wv.w = (1.0f - alpha) * Wv.w + Sv.w;
        ((float4*)S2)[f4] = Sv;
        ((float4*)W2)[f4] = Wv;
        ((float4*)W2tf)[f4] = make_float4(f2tff(Wv.x), f2tff(Wv.y), f2tff(Wv.z), f2tff(Wv.w));
    }
}

__global__ void __launch_bounds__(256) ro1_kernel(
    const float* __restrict__ q, const float* __restrict__ W1tf, float* __restrict__ af) {
    gemm_big<2>(q, W1tf, af, H, D, blockIdx.x, blockIdx.y);
}
__global__ void __launch_bounds__(256) ro2_kernel(
    const float* __restrict__ af, const float* __restrict__ W2tf, float* __restrict__ out) {
    gemm_big<0>(af, W2tf, out, D, H, blockIdx.x, blockIdx.y);
}

// ---------------- launch ---------------------------------------------------------
extern "C" void kernel_launch(void* const* d_in, const int* in_sizes, int n_in,
                              void* d_out, int out_size) {
    const float* x    = (const float*)d_in[0];
    const float* w_q  = (const float*)d_in[1];
    const float* w_k  = (const float*)d_in[2];
    const float* w_v  = (const float*)d_in[3];
    const float* mw1  = (const float*)d_in[4];
    const float* mw2  = (const float*)d_in[5];
    const float* a_t  = (const float*)d_in[6];
    const float* l_t  = (const float*)d_in[7];
    const float* dc_t = (const float*)d_in[8];
    const int*   um   = (const int*)  d_in[9];
    float* out = (float*)d_out;

    static bool init_done = false;
    static cudaStream_t s1 = nullptr;
    static cudaEvent_t ev_fork, ev_dh, ev_g2, ev_w2;
    if (!init_done) {
        cudaFuncSetAttribute(proj_kernel, cudaFuncAttributeMaxDynamicSharedMemorySize, BIG_SMEM_BYTES);
        cudaFuncSetAttribute(ro1_kernel,  cudaFuncAttributeMaxDynamicSharedMemorySize, BIG_SMEM_BYTES);
        cudaFuncSetAttribute(ro2_kernel,  cudaFuncAttributeMaxDynamicSharedMemorySize, BIG_SMEM_BYTES);
        cudaFuncSetAttribute(h_kernel,    cudaFuncAttributeMaxDynamicSharedMemorySize, SMEM_BYTES);
        cudaFuncSetAttribute(e_kernel,    cudaFuncAttributeMaxDynamicSharedMemorySize, SMEM_BYTES);
        cudaFuncSetAttribute(dh_kernel,   cudaFuncAttributeMaxDynamicSharedMemorySize, SMEM_BYTES);
        cudaFuncSetAttribute(g2_kernel,   cudaFuncAttributeMaxDynamicSharedMemorySize, SMEM_BYTES);
        cudaFuncSetAttribute(g1upd_kernel, cudaFuncAttributeMaxDynamicSharedMemorySize, SMEM_BYTES);
        cudaStreamCreateWithFlags(&s1, cudaStreamNonBlocking);
        cudaEventCreateWithFlags(&ev_fork, cudaEventDisableTiming);
        cudaEventCreateWithFlags(&ev_dh,   cudaEventDisableTiming);
        cudaEventCreateWithFlags(&ev_g2,   cudaEventDisableTiming);
        cudaEventCreateWithFlags(&ev_w2,   cudaEventDisableTiming);
        init_done = true;
    }

    float *W1, *W2, *W1tf, *W2tf, *S1, *S2, *g2, *xtf, *wktf, *wvtf, *wqtf;
    float *kall, *vall, *q_, *h_, *a_, *e_, *dh_, *af_;
    cudaGetSymbolAddress((void**)&W1,   g_W1);
    cudaGetSymbolAddress((void**)&W2,   g_W2);
    cudaGetSymbolAddress((void**)&W1tf, g_W1tf);
    cudaGetSymbolAddress((void**)&W2tf, g_W2tf);
    cudaGetSymbolAddress((void**)&S1,   g_S1);
    cudaGetSymbolAddress((void**)&S2,   g_S2);
    cudaGetSymbolAddress((void**)&g2,   g_g2);
    cudaGetSymbolAddress((void**)&xtf,  g_xtf);
    cudaGetSymbolAddress((void**)&wktf, g_wktf);
    cudaGetSymbolAddress((void**)&wvtf, g_wvtf);
    cudaGetSymbolAddress((void**)&wqtf, g_wqtf);
    cudaGetSymbolAddress((void**)&kall, g_kall);
    cudaGetSymbolAddress((void**)&vall, g_vall);
    cudaGetSymbolAddress((void**)&q_,   g_q);
    cudaGetSymbolAddress((void**)&h_,   g_h);
    cudaGetSymbolAddress((void**)&a_,   g_a);
    cudaGetSymbolAddress((void**)&e_,   g_e);
    cudaGetSymbolAddress((void**)&dh_,  g_dh);
    cudaGetSymbolAddress((void**)&af_,  g_af);

    cudaMemcpyAsync(W1, mw1, sizeof(float) * D * H, cudaMemcpyDeviceToDevice);
    cudaMemcpyAsync(W2, mw2, sizeof(float) * H * D, cudaMemcpyDeviceToDevice);
    cudaMemsetAsync(S1, 0, sizeof(float) * D * H);
    cudaMemsetAsync(S2, 0, sizeof(float) * H * D);

    cvt_all_kernel<<<(CVT_TOTAL + 255) / 256, 256>>>(
        (const float4*)x, (const float4*)w_k, (const float4*)w_v, (const float4*)w_q,
        (const float4*)mw1, (const float4*)mw2,
        (float4*)xtf, (float4*)wktf, (float4*)wvtf, (float4*)wqtf,
        (float4*)W1tf, (float4*)W2tf);

    const float escale = 2.0f / (float)(NROWS * D);

    proj_kernel<<<dim3(D / 128, TOTROWS / 128, 3), 256, BIG_SMEM_BYTES>>>(
        xtf, wktf, wvtf, wqtf, kall, vall, q_);

    for (int t = 0; t < NCHUNK; ++t) {
        // h_t: waits g2_{t-1} (a/e buffer reuse)
        if (t > 0) cudaStreamWaitEvent(0, ev_g2, 0);
        h_kernel<<<dim3(H / 64, NROWS / 64), 128, SMEM_BYTES>>>(kall, W1tf, a_, h_, t);
        // e_t: waits w2upd_{t-1} (W2tf consumer)
        if (t > 0) cudaStreamWaitEvent(0, ev_w2, 0);
        e_kernel<<<dim3(D / 64, NROWS / 64), 128, SMEM_BYTES>>>(a_, W2tf, e_, vall, escale, t);
        cudaEventRecord(ev_fork, 0);
        // stream1: g2 (overlaps dh + g1upd), then W2/S2 apply after dh releases W2tf
        cudaStreamWaitEvent(s1, ev_fork, 0);
        g2_kernel<<<dim3(D / 64, H / 64), 128, SMEM_BYTES, s1>>>(a_, e_, g2);
        cudaEventRecord(ev_g2, s1);
        // stream0 critical path
        dh_kernel<<<dim3(H / 64, NROWS / 64), 128, SMEM_BYTES>>>(e_, W2tf, dh_, h_);
        cudaEventRecord(ev_dh, 0);
        g1upd_kernel<<<dim3(H / 64, D / 64), 128, SMEM_BYTES>>>(
            kall, dh_, W1, S1, W1tf, a_t, l_t, dc_t, um, t);
        // stream1: W2 apply once dh has consumed old W2tf
        cudaStreamWaitEvent(s1, ev_dh, 0);
        w2upd_kernel<<<128, 256, 0, s1>>>(W2, S2, W2tf, g2, a_t, l_t, dc_t, um);
        cudaEventRecord(ev_w2, s1);
    }
    cudaStreamWaitEvent(0, ev_w2, 0);   // final join (W2tf for ro2)

    ro1_kernel<<<dim3(H / 128, TOTROWS / 128), 256, BIG_SMEM_BYTES>>>(q_, W1tf, af_);
    ro2_kernel<<<dim3(D / 128, TOTROWS / 128), 256, BIG_SMEM_BYTES>>>(af_, W2tf, out);
}